// round 15
// baseline (speedup 1.0000x reference)
#include <cuda_runtime.h>
#include <cuda_bf16.h>
#include <cstdint>
#include <stdint.h>
#include <math.h>

// Problem constants (fixed by the reference):
//   B=1, T_OUT=8, L=512 -> S=4096 tokens, D=512, H=8 heads, hd=64
#define S_TOK   4096
#define D_MODEL 512
#define NH      8
#define HD      64

// Scratch (device globals: allocation-free, graph-safe).
__device__ __nv_bfloat16 g_xb[S_TOK * D_MODEL];       // x in bf16
__device__ __nv_bfloat16 g_wb[4 * D_MODEL * D_MODEL]; // Wq|Wk|Wv|Wo in bf16
__device__ __nv_bfloat16 g_qb[NH * S_TOK * HD];       // q, CAPE'd, scaled
__device__ __nv_bfloat16 g_kb[NH * S_TOK * HD];       // k, CAPE'd
__device__ __nv_bfloat16 g_vb[NH * S_TOK * HD];       // v
__device__ __nv_bfloat16 g_ob[S_TOK * D_MODEL];       // attention out (S, D)

// ----------------------------------------------------------------------------
// PTX helpers
// ----------------------------------------------------------------------------
__device__ __forceinline__ uint32_t smem_u32(const void* p) {
    return (uint32_t)__cvta_generic_to_shared(p);
}
__device__ __forceinline__ void ldsm_x4(uint32_t* r, uint32_t a) {
    asm volatile("ldmatrix.sync.aligned.m8n8.x4.shared.b16 {%0,%1,%2,%3}, [%4];"
                 : "=r"(r[0]), "=r"(r[1]), "=r"(r[2]), "=r"(r[3]) : "r"(a));
}
__device__ __forceinline__ void ldsm_x4_t(uint32_t* r, uint32_t a) {
    asm volatile("ldmatrix.sync.aligned.m8n8.x4.trans.shared.b16 {%0,%1,%2,%3}, [%4];"
                 : "=r"(r[0]), "=r"(r[1]), "=r"(r[2]), "=r"(r[3]) : "r"(a));
}
__device__ __forceinline__ void mma_bf16(float* c, const uint32_t* a,
                                         uint32_t b0, uint32_t b1) {
    asm volatile(
        "mma.sync.aligned.m16n8k16.row.col.f32.bf16.bf16.f32 "
        "{%0,%1,%2,%3}, {%4,%5,%6,%7}, {%8,%9}, {%0,%1,%2,%3};"
        : "+f"(c[0]), "+f"(c[1]), "+f"(c[2]), "+f"(c[3])
        : "r"(a[0]), "r"(a[1]), "r"(a[2]), "r"(a[3]), "r"(b0), "r"(b1));
}
__device__ __forceinline__ uint32_t pack_bf16x2(float a, float b) {
    __nv_bfloat162 t = __floats2bfloat162_rn(a, b);
    return *reinterpret_cast<uint32_t*>(&t);
}
__device__ __forceinline__ void cp_async16(uint32_t dst, const void* src) {
    asm volatile("cp.async.cg.shared.global [%0], [%1], 16;"
                 :: "r"(dst), "l"(src));
}
__device__ __forceinline__ void cp_commit() {
    asm volatile("cp.async.commit_group;");
}
template <int N>
__device__ __forceinline__ void cp_wait() {
    asm volatile("cp.async.wait_group %0;" :: "n"(N));
}

// ============================================================================
// Kernel 0: fp32 -> bf16 conversion of x and all weights (streaming).
//   Virtual concat [x | Wq | Wk | Wv | Wo], 8 elems/thread. 1536 blocks x 256.
// ============================================================================
#define X_CHUNKS  (S_TOK * D_MODEL / 8)            // 262144
#define W_CHUNKS  (D_MODEL * D_MODEL / 8)          // 32768

__global__ void __launch_bounds__(256) convert_kernel(
    const float* __restrict__ x,
    const float* __restrict__ Wq, const float* __restrict__ Wk,
    const float* __restrict__ Wv, const float* __restrict__ Wo)
{
    const int gid = blockIdx.x * 256 + threadIdx.x;   // chunk index (8 elems)
    const float* src;
    __nv_bfloat16* dst;
    int off;
    if (gid < X_CHUNKS)                     { src = x;  dst = g_xb;                          off = gid; }
    else if (gid < X_CHUNKS + W_CHUNKS)     { src = Wq; dst = g_wb;                          off = gid - X_CHUNKS; }
    else if (gid < X_CHUNKS + 2 * W_CHUNKS) { src = Wk; dst = g_wb + D_MODEL * D_MODEL;      off = gid - X_CHUNKS - W_CHUNKS; }
    else if (gid < X_CHUNKS + 3 * W_CHUNKS) { src = Wv; dst = g_wb + 2 * D_MODEL * D_MODEL;  off = gid - X_CHUNKS - 2 * W_CHUNKS; }
    else                                    { src = Wo; dst = g_wb + 3 * D_MODEL * D_MODEL;  off = gid - X_CHUNKS - 3 * W_CHUNKS; }

    const float4* s = reinterpret_cast<const float4*>(src) + (size_t)off * 2;
    const float4 f0 = s[0], f1 = s[1];
    uint4 d;
    d.x = pack_bf16x2(f0.x, f0.y); d.y = pack_bf16x2(f0.z, f0.w);
    d.z = pack_bf16x2(f1.x, f1.y); d.w = pack_bf16x2(f1.z, f1.w);
    *reinterpret_cast<uint4*>(dst + (size_t)off * 8) = d;
}

// ============================================================================
// Kernel 1: QKV projection, cp.async double-buffered bf16 tiles.
//   BM=128, BN=64, BK=64; 256 threads; 2 CTAs/SM; grid (8, 32, 3).
//   smem: a[2][128*64] + b[2][64*64] bf16 = 49152 B dynamic.
// ============================================================================
#define QKV_SMEM_BYTES ((2 * 128 * 64 + 2 * 64 * 64) * 2)   // 49152

__global__ void __launch_bounds__(256, 2) qkv_mma_kernel(
    const float* __restrict__ p_out, const float* __restrict__ p_out_inv)
{
    extern __shared__ __nv_bfloat16 smq[];
    __nv_bfloat16* a_b[2] = { smq,          smq + 8192 };
    __nv_bfloat16* b_b[2] = { smq + 16384,  smq + 16384 + 4096 };

    const int mode = blockIdx.z;   // 0=q, 1=k, 2=v
    const __nv_bfloat16* __restrict__ W = g_wb + (size_t)mode * D_MODEL * D_MODEL;
    __nv_bfloat16* __restrict__ out =
        (mode == 0) ? g_qb : (mode == 1) ? g_kb : g_vb;
    const float* __restrict__ Pm = (mode == 0) ? p_out_inv : p_out;

    const int tid  = threadIdx.x;
    const int lane = tid & 31;
    const int w    = tid >> 5;
    const int m0   = blockIdx.y * 128;
    const int n0   = blockIdx.x * 64;

    // stage A(128x64)+B(64x64) bf16 tiles for k-step `ks` into buffer `buf`
    auto stage = [&](int ks, int buf) {
        const int k0 = ks * 64;
#pragma unroll
        for (int u = 0; u < 4; u++) {
            const int gid = u * 256 + tid;      // 0..1023 chunks (A)
            const int row = gid >> 3;
            const int c8  = gid & 7;
            cp_async16(smem_u32(a_b[buf] + row * 64 + ((c8 ^ (row & 7)) << 3)),
                       g_xb + (size_t)(m0 + row) * D_MODEL + k0 + c8 * 8);
        }
#pragma unroll
        for (int u = 0; u < 2; u++) {
            const int gid = u * 256 + tid;      // 0..511 chunks (B)
            const int row = gid >> 3;
            const int c8  = gid & 7;
            cp_async16(smem_u32(b_b[buf] + row * 64 + ((c8 ^ (row & 7)) << 3)),
                       W + (size_t)(k0 + row) * D_MODEL + n0 + c8 * 8);
        }
    };

    float cf[8][4];
#pragma unroll
    for (int nt = 0; nt < 8; nt++)
#pragma unroll
        for (int c = 0; c < 4; c++) cf[nt][c] = 0.f;

    stage(0, 0);
    cp_commit();

    const int NKS = D_MODEL / 64;   // 8
    for (int ks = 0; ks < NKS; ks++) {
        const int buf = ks & 1;
        if (ks + 1 < NKS) {
            stage(ks + 1, buf ^ 1);
            cp_commit();
            cp_wait<1>();
        } else {
            cp_wait<0>();
        }
        __syncthreads();

        const __nv_bfloat16* a_s = a_b[buf];
        const __nv_bfloat16* b_s = b_b[buf];

        uint32_t qa[4][4];
        {
            const int mi = lane >> 3, rr = lane & 7;
            const int arow = w * 16 + ((mi & 1) << 3) + rr;
#pragma unroll
            for (int kt = 0; kt < 4; kt++) {
                const int ch = (kt * 2 + (mi >> 1)) ^ (arow & 7);
                ldsm_x4(qa[kt], smem_u32(a_s + arow * 64 + ch * 8));
            }
        }
        {
            const int j = lane >> 3, rr = lane & 7;
#pragma unroll
            for (int nt = 0; nt < 8; nt++) {
#pragma unroll
                for (int kt2 = 0; kt2 < 2; kt2++) {
                    const int brow = kt2 * 32 + j * 8 + rr;
                    const int ch = nt ^ (brow & 7);
                    uint32_t vb[4];
                    ldsm_x4_t(vb, smem_u32(b_s + brow * 64 + ch * 8));
                    mma_bf16(cf[nt], qa[kt2 * 2],     vb[0], vb[1]);
                    mma_bf16(cf[nt], qa[kt2 * 2 + 1], vb[2], vb[3]);
                }
            }
        }
        __syncthreads();
    }

    // ---- CAPE epilogue (q,k): mix 4-col groups via shfl_xor(1). ----
    if (mode < 2) {
        const float* P = Pm + (m0 >> 9) * 16;
        float pm[16];
#pragma unroll
        for (int t = 0; t < 16; t++) pm[t] = P[t];
        const int gb = (lane & 1) * 2;
#pragma unroll
        for (int nt = 0; nt < 8; nt++) {
#pragma unroll
            for (int hf = 0; hf < 2; hf++) {
                const float v0 = cf[nt][hf * 2], v1 = cf[nt][hf * 2 + 1];
                const float p0 = __shfl_xor_sync(0xffffffffu, v0, 1);
                const float p1 = __shfl_xor_sync(0xffffffffu, v1, 1);
                const float a0 = (lane & 1) ? p0 : v0;
                const float a1 = (lane & 1) ? p1 : v1;
                const float a2 = (lane & 1) ? v0 : p0;
                const float a3 = (lane & 1) ? v1 : p1;
                cf[nt][hf * 2]     = a0 * pm[gb]     + a1 * pm[4 + gb]
                                   + a2 * pm[8 + gb] + a3 * pm[12 + gb];
                cf[nt][hf * 2 + 1] = a0 * pm[gb + 1]     + a1 * pm[4 + gb + 1]
                                   + a2 * pm[8 + gb + 1] + a3 * pm[12 + gb + 1];
            }
        }
    }
    if (mode == 0) {   // softmax scale * log2(e): 0.125 * 1.4426950
#pragma unroll
        for (int nt = 0; nt < 8; nt++)
#pragma unroll
            for (int c = 0; c < 4; c++) cf[nt][c] *= 0.18033688f;
    }

    const int row0 = m0 + w * 16 + (lane >> 2);
    const int row1 = row0 + 8;
#pragma unroll
    for (int nt = 0; nt < 8; nt++) {
        const int ng = n0 + nt * 8 + (lane & 3) * 2;
        const int h  = ng >> 6;
        const int c  = ng & 63;
        *reinterpret_cast<uint32_t*>(out + ((size_t)h * S_TOK + row0) * HD + c) =
            pack_bf16x2(cf[nt][0], cf[nt][1]);
        *reinterpret_cast<uint32_t*>(out + ((size_t)h * S_TOK + row1) * HD + c) =
            pack_bf16x2(cf[nt][2], cf[nt][3]);
    }
}

// ============================================================================
// Kernel 2: flash attention. Br=64, Bc=128, 4 warps, 3 CTAs/SM (was 2).
//   cp.async double-buffered K/V. smem 72KB x3 = 216KB/SM (fits 227KB).
// ============================================================================
#define ATTN_SMEM_BYTES ((64 * 64 + 4 * 128 * 64) * 2)   // 73728 B

__global__ void __launch_bounds__(128, 3) attn_kernel()
{
    extern __shared__ __nv_bfloat16 sm[];
    __nv_bfloat16* q_s = sm;
    __nv_bfloat16* k_b[2] = { sm + 4096,  sm + 4096 + 8192 };
    __nv_bfloat16* v_b[2] = { sm + 20480, sm + 20480 + 8192 };

    const int tid  = threadIdx.x;
    const int lane = tid & 31;
    const int w    = tid >> 5;
    const int h    = blockIdx.y;
    const int m0   = blockIdx.x * 64;

    const __nv_bfloat16* __restrict__ qg = g_qb + (size_t)h * S_TOK * HD;
    const __nv_bfloat16* __restrict__ kg = g_kb + (size_t)h * S_TOK * HD;
    const __nv_bfloat16* __restrict__ vg = g_vb + (size_t)h * S_TOK * HD;

    auto stage_kv = [&](int it, int buf) {
        const __nv_bfloat16* ks = kg + (size_t)(it * 128) * HD;
        const __nv_bfloat16* vs = vg + (size_t)(it * 128) * HD;
#pragma unroll
        for (int u = 0; u < 8; u++) {
            const int gid = u * 128 + tid;
            const int row = gid >> 3;
            const int c8  = gid & 7;
            const int so  = row * 64 + ((c8 ^ (row & 7)) << 3);
            cp_async16(smem_u32(k_b[buf] + so), ks + row * 64 + c8 * 8);
            cp_async16(smem_u32(v_b[buf] + so), vs + row * 64 + c8 * 8);
        }
    };

#pragma unroll
    for (int u = 0; u < 4; u++) {
        const int gid = u * 128 + tid;
        const int row = gid >> 3;
        const int c8  = gid & 7;
        uint4 d = *reinterpret_cast<const uint4*>(
            qg + (size_t)(m0 + row) * HD + c8 * 8);
        *reinterpret_cast<uint4*>(q_s + row * 64 + ((c8 ^ (row & 7)) << 3)) = d;
    }
    stage_kv(0, 0);
    cp_commit();
    __syncthreads();

    uint32_t qa[4][4];
    {
        const int mi = lane >> 3, rr = lane & 7;
        const int row = w * 16 + ((mi & 1) << 3) + rr;
#pragma unroll
        for (int kt = 0; kt < 4; kt++) {
            const int ch = (kt * 2 + (mi >> 1)) ^ (row & 7);
            ldsm_x4(qa[kt], smem_u32(q_s + row * 64 + ch * 8));
        }
    }

    float m_i0 = -1e30f, m_i1 = -1e30f, l0 = 0.f, l1 = 0.f;
    float of[8][4];
#pragma unroll
    for (int nt = 0; nt < 8; nt++)
#pragma unroll
        for (int c = 0; c < 4; c++) of[nt][c] = 0.f;

    const int NIT = S_TOK / 128;   // 32
    for (int it = 0; it < NIT; it++) {
        const int buf = it & 1;
        if (it + 1 < NIT) {
            stage_kv(it + 1, buf ^ 1);
            cp_commit();
            cp_wait<1>();
        } else {
            cp_wait<0>();
        }
        __syncthreads();

        const __nv_bfloat16* k_s = k_b[buf];
        const __nv_bfloat16* v_s = v_b[buf];

        float sf[16][4];
#pragma unroll
        for (int nt = 0; nt < 16; nt++)
#pragma unroll
            for (int c = 0; c < 4; c++) sf[nt][c] = 0.f;

        {
            const int j = lane >> 3, rr = lane & 7;
#pragma unroll
            for (int nt = 0; nt < 16; nt++) {
                const int srow = nt * 8 + rr;
                uint32_t b[8];
                const int ch0 = (j)     ^ (srow & 7);
                const int ch1 = (4 + j) ^ (srow & 7);
                ldsm_x4(b,     smem_u32(k_s + srow * 64 + ch0 * 8));
                ldsm_x4(b + 4, smem_u32(k_s + srow * 64 + ch1 * 8));
                mma_bf16(sf[nt], qa[0], b[0], b[1]);
                mma_bf16(sf[nt], qa[1], b[2], b[3]);
                mma_bf16(sf[nt], qa[2], b[4], b[5]);
                mma_bf16(sf[nt], qa[3], b[6], b[7]);
            }
        }

        float mx0 = sf[0][0], mx1 = sf[0][2];
#pragma unroll
        for (int nt = 0; nt < 16; nt++) {
            mx0 = fmaxf(mx0, fmaxf(sf[nt][0], sf[nt][1]));
            mx1 = fmaxf(mx1, fmaxf(sf[nt][2], sf[nt][3]));
        }
        mx0 = fmaxf(mx0, __shfl_xor_sync(0xffffffffu, mx0, 1));
        mx0 = fmaxf(mx0, __shfl_xor_sync(0xffffffffu, mx0, 2));
        mx1 = fmaxf(mx1, __shfl_xor_sync(0xffffffffu, mx1, 1));
        mx1 = fmaxf(mx1, __shfl_xor_sync(0xffffffffu, mx1, 2));

        const float mn0 = fmaxf(m_i0, mx0);
        const float mn1 = fmaxf(m_i1, mx1);
        const float al0 = exp2f(m_i0 - mn0);
        const float al1 = exp2f(m_i1 - mn1);
        m_i0 = mn0; m_i1 = mn1;

        float rs0 = 0.f, rs1 = 0.f;
        uint32_t pa[8][4];
#pragma unroll
        for (int nt = 0; nt < 16; nt++) {
            const float e0 = exp2f(sf[nt][0] - mn0);
            const float e1 = exp2f(sf[nt][1] - mn0);
            const float e2 = exp2f(sf[nt][2] - mn1);
            const float e3 = exp2f(sf[nt][3] - mn1);
            rs0 += e0 + e1; rs1 += e2 + e3;
            const uint32_t p01 = pack_bf16x2(e0, e1);
            const uint32_t p23 = pack_bf16x2(e2, e3);
            const int jt = nt >> 1;
            if ((nt & 1) == 0) { pa[jt][0] = p01; pa[jt][1] = p23; }
            else               { pa[jt][2] = p01; pa[jt][3] = p23; }
        }
        rs0 += __shfl_xor_sync(0xffffffffu, rs0, 1);
        rs0 += __shfl_xor_sync(0xffffffffu, rs0, 2);
        rs1 += __shfl_xor_sync(0xffffffffu, rs1, 1);
        rs1 += __shfl_xor_sync(0xffffffffu, rs1, 2);
        l0 = l0 * al0 + rs0;
        l1 = l1 * al1 + rs1;

#pragma unroll
        for (int nt = 0; nt < 8; nt++) {
            of[nt][0] *= al0; of[nt][1] *= al0;
            of[nt][2] *= al1; of[nt][3] *= al1;
        }

        {
            const int j = lane >> 3, rr = lane & 7;
#pragma unroll
            for (int kt2 = 0; kt2 < 4; kt2++) {
                const int vrow = kt2 * 32 + j * 8 + rr;
#pragma unroll
                for (int nt = 0; nt < 8; nt++) {
                    uint32_t vb[4];
                    const int ch = nt ^ (vrow & 7);
                    ldsm_x4_t(vb, smem_u32(v_s + vrow * 64 + ch * 8));
                    mma_bf16(of[nt], pa[2 * kt2],     vb[0], vb[1]);
                    mma_bf16(of[nt], pa[2 * kt2 + 1], vb[2], vb[3]);
                }
            }
        }
        __syncthreads();
    }

    const float inv0 = 1.0f / l0;
    const float inv1 = 1.0f / l1;
    const int row0 = m0 + w * 16 + (lane >> 2);
    const int row1 = row0 + 8;
    const int cbase = h * HD + (lane & 3) * 2;
#pragma unroll
    for (int nt = 0; nt < 8; nt++) {
        const int col = cbase + nt * 8;
        *reinterpret_cast<uint32_t*>(g_ob + (size_t)row0 * D_MODEL + col) =
            pack_bf16x2(of[nt][0] * inv0, of[nt][1] * inv0);
        *reinterpret_cast<uint32_t*>(g_ob + (size_t)row1 * D_MODEL + col) =
            pack_bf16x2(of[nt][2] * inv1, of[nt][3] * inv1);
    }
}

// ============================================================================
// Kernel 3: output projection, cp.async double-buffered; bias + residual.
//   BM=128, BN=128, BK=64; 256 threads; grid (4, 32). smem 64KB dynamic.
// ============================================================================
#define PROJ_SMEM_BYTES ((2 * 128 * 64 + 2 * 64 * 128) * 2)   // 65536

__global__ void __launch_bounds__(256) proj_mma_kernel(
    const float* __restrict__ bo,
    const float* __restrict__ hs, float* __restrict__ outp)
{
    extern __shared__ __nv_bfloat16 smp[];
    __nv_bfloat16* a_b[2] = { smp,          smp + 8192 };
    __nv_bfloat16* b_b[2] = { smp + 16384,  smp + 16384 + 8192 };

    const __nv_bfloat16* __restrict__ Wo = g_wb + (size_t)3 * D_MODEL * D_MODEL;

    const int tid  = threadIdx.x;
    const int lane = tid & 31;
    const int w    = tid >> 5;
    const int m0   = blockIdx.y * 128;
    const int n0   = blockIdx.x * 128;

    auto stage = [&](int ks, int buf) {
        const int k0 = ks * 64;
#pragma unroll
        for (int u = 0; u < 4; u++) {
            const int gid = u * 256 + tid;      // A: 128x64, 1024 chunks
            const int row = gid >> 3;
            const int c8  = gid & 7;
            cp_async16(smem_u32(a_b[buf] + row * 64 + ((c8 ^ (row & 7)) << 3)),
                       g_ob + (size_t)(m0 + row) * D_MODEL + k0 + c8 * 8);
        }
#pragma unroll
        for (int u = 0; u < 4; u++) {
            const int gid = u * 256 + tid;      // B: 64x128, 1024 chunks
            const int row = gid >> 4;
            const int c16 = gid & 15;
            cp_async16(smem_u32(b_b[buf] + row * 128 + ((c16 ^ (row & 7)) << 3)),
                       Wo + (size_t)(k0 + row) * D_MODEL + n0 + c16 * 8);
        }
    };

    float cf[16][4];
#pragma unroll
    for (int nt = 0; nt < 16; nt++)
#pragma unroll
        for (int c = 0; c < 4; c++) cf[nt][c] = 0.f;

    stage(0, 0);
    cp_commit();

    const int NKS = D_MODEL / 64;   // 8
    for (int ks = 0; ks < NKS; ks++) {
        const int buf = ks & 1;
        if (ks + 1 < NKS) {
            stage(ks + 1, buf ^ 1);
            cp_commit();
            cp_wait<1>();
        } else {
            cp_wait<0>();
        }
        __syncthreads();

        const __nv_bfloat16* a_s = a_b[buf];
        const __nv_bfloat16* b_s = b_b[buf];

        uint32_t qa[4][4];
        {
            const int mi = lane >> 3, rr = lane & 7;
            const int arow = w * 16 + ((mi & 1) << 3) + rr;
#pragma unroll
            for (int kt = 0; kt < 4; kt++) {
                const int ch = (kt * 2 + (mi >> 1)) ^ (arow & 7);
                ldsm_x4(qa[kt], smem_u32(a_s + arow * 64 + ch * 8));
            }
        }
        {
            const int j = lane >> 3, rr = lane & 7;
#pragma unroll
            for (int nt = 0; nt < 16; nt++) {
#pragma unroll
                for (int kt2 = 0; kt2 < 2; kt2++) {
                    const int brow = kt2 * 32 + j * 8 + rr;
                    const int ch = nt ^ (brow & 7);
                    uint32_t vb[4];
                    ldsm_x4_t(vb, smem_u32(b_s + brow * 128 + ch * 8));
                    mma_bf16(cf[nt], qa[kt2 * 2],     vb[0], vb[1]);
                    mma_bf16(cf[nt], qa[kt2 * 2 + 1], vb[2], vb[3]);
                }
            }
        }
        __syncthreads();
    }

    // ---- epilogue: + bias + residual, fp32 out ----
    const int row0 = m0 + w * 16 + (lane >> 2);
    const int row1 = row0 + 8;
#pragma unroll
    for (int nt = 0; nt < 16; nt++) {
        const int col = n0 + nt * 8 + (lane & 3) * 2;
        const float2 bb = *reinterpret_cast<const float2*>(bo + col);
        const float2 r0 = *reinterpret_cast<const float2*>(
            hs + (size_t)row0 * D_MODEL + col);
        const float2 r1 = *reinterpret_cast<const float2*>(
            hs + (size_t)row1 * D_MODEL + col);
        *reinterpret_cast<float2*>(outp + (size_t)row0 * D_MODEL + col) =
            make_float2(cf[nt][0] + bb.x + r0.x, cf[nt][1] + bb.y + r0.y);
        *reinterpret_cast<float2*>(outp + (size_t)row1 * D_MODEL + col) =
            make_float2(cf[nt][2] + bb.x + r1.x, cf[nt][3] + bb.y + r1.y);
    }
}

// ============================================================================
// Launch
// ============================================================================
extern "C" void kernel_launch(void* const* d_in, const int* in_sizes, int n_in,
                              void* d_out, int out_size)
{
    const float* hs        = (const float*)d_in[0];
    const float* p_out     = (const float*)d_in[1];
    const float* p_out_inv = (const float*)d_in[2];
    const float* Wq        = (const float*)d_in[3];
    const float* Wk        = (const float*)d_in[4];
    const float* Wv        = (const float*)d_in[5];
    const float* Wo        = (const float*)d_in[6];
    const float* bo        = (const float*)d_in[7];
    float* out             = (float*)d_out;

    // >48KB dynamic smem opt-ins (host attributes; idempotent, graph-safe).
    cudaFuncSetAttribute(attn_kernel,
                         cudaFuncAttributeMaxDynamicSharedMemorySize,
                         ATTN_SMEM_BYTES);
    cudaFuncSetAttribute(proj_mma_kernel,
                         cudaFuncAttributeMaxDynamicSharedMemorySize,
                         PROJ_SMEM_BYTES);
    cudaFuncSetAttribute(qkv_mma_kernel,
                         cudaFuncAttributeMaxDynamicSharedMemorySize,
                         QKV_SMEM_BYTES);

    convert_kernel<<<1536, 256>>>(hs, Wq, Wk, Wv, Wo);
    qkv_mma_kernel<<<dim3(8, 32, 3), 256, QKV_SMEM_BYTES>>>(p_out, p_out_inv);
    attn_kernel<<<dim3(64, 8), 128, ATTN_SMEM_BYTES>>>();
    proj_mma_kernel<<<dim3(4, 32), 256, PROJ_SMEM_BYTES>>>(bo, hs, out);
}

// round 16
// speedup vs baseline: 1.1062x; 1.1062x over previous
#include <cuda_runtime.h>
#include <cuda_bf16.h>
#include <cstdint>
#include <stdint.h>
#include <math.h>

// Problem constants (fixed by the reference):
//   B=1, T_OUT=8, L=512 -> S=4096 tokens, D=512, H=8 heads, hd=64
#define S_TOK   4096
#define D_MODEL 512
#define NH      8
#define HD      64

// Scratch (device globals: allocation-free, graph-safe).
__device__ __nv_bfloat16 g_xb[S_TOK * D_MODEL];       // x in bf16
__device__ __nv_bfloat16 g_wb[4 * D_MODEL * D_MODEL]; // Wq|Wk|Wv|Wo in bf16
__device__ __nv_bfloat16 g_qb[NH * S_TOK * HD];       // q, CAPE'd, scaled
__device__ __nv_bfloat16 g_kb[NH * S_TOK * HD];       // k, CAPE'd
__device__ __nv_bfloat16 g_vb[NH * S_TOK * HD];       // v
__device__ __nv_bfloat16 g_ob[S_TOK * D_MODEL];       // attention out (S, D)

// ----------------------------------------------------------------------------
// PTX helpers
// ----------------------------------------------------------------------------
__device__ __forceinline__ uint32_t smem_u32(const void* p) {
    return (uint32_t)__cvta_generic_to_shared(p);
}
__device__ __forceinline__ void ldsm_x4(uint32_t* r, uint32_t a) {
    asm volatile("ldmatrix.sync.aligned.m8n8.x4.shared.b16 {%0,%1,%2,%3}, [%4];"
                 : "=r"(r[0]), "=r"(r[1]), "=r"(r[2]), "=r"(r[3]) : "r"(a));
}
__device__ __forceinline__ void ldsm_x4_t(uint32_t* r, uint32_t a) {
    asm volatile("ldmatrix.sync.aligned.m8n8.x4.trans.shared.b16 {%0,%1,%2,%3}, [%4];"
                 : "=r"(r[0]), "=r"(r[1]), "=r"(r[2]), "=r"(r[3]) : "r"(a));
}
__device__ __forceinline__ void mma_bf16(float* c, const uint32_t* a,
                                         uint32_t b0, uint32_t b1) {
    asm volatile(
        "mma.sync.aligned.m16n8k16.row.col.f32.bf16.bf16.f32 "
        "{%0,%1,%2,%3}, {%4,%5,%6,%7}, {%8,%9}, {%0,%1,%2,%3};"
        : "+f"(c[0]), "+f"(c[1]), "+f"(c[2]), "+f"(c[3])
        : "r"(a[0]), "r"(a[1]), "r"(a[2]), "r"(a[3]), "r"(b0), "r"(b1));
}
__device__ __forceinline__ uint32_t pack_bf16x2(float a, float b) {
    __nv_bfloat162 t = __floats2bfloat162_rn(a, b);
    return *reinterpret_cast<uint32_t*>(&t);
}
__device__ __forceinline__ void cp_async16(uint32_t dst, const void* src) {
    asm volatile("cp.async.cg.shared.global [%0], [%1], 16;"
                 :: "r"(dst), "l"(src));
}
__device__ __forceinline__ void cp_commit() {
    asm volatile("cp.async.commit_group;");
}
template <int N>
__device__ __forceinline__ void cp_wait() {
    asm volatile("cp.async.wait_group %0;" :: "n"(N));
}

// ============================================================================
// Kernel 0: fp32 -> bf16 conversion of x and all weights (streaming).
// ============================================================================
#define X_CHUNKS  (S_TOK * D_MODEL / 8)            // 262144
#define W_CHUNKS  (D_MODEL * D_MODEL / 8)          // 32768

__global__ void __launch_bounds__(256) convert_kernel(
    const float* __restrict__ x,
    const float* __restrict__ Wq, const float* __restrict__ Wk,
    const float* __restrict__ Wv, const float* __restrict__ Wo)
{
    const int gid = blockIdx.x * 256 + threadIdx.x;   // chunk index (8 elems)
    const float* src;
    __nv_bfloat16* dst;
    int off;
    if (gid < X_CHUNKS)                     { src = x;  dst = g_xb;                          off = gid; }
    else if (gid < X_CHUNKS + W_CHUNKS)     { src = Wq; dst = g_wb;                          off = gid - X_CHUNKS; }
    else if (gid < X_CHUNKS + 2 * W_CHUNKS) { src = Wk; dst = g_wb + D_MODEL * D_MODEL;      off = gid - X_CHUNKS - W_CHUNKS; }
    else if (gid < X_CHUNKS + 3 * W_CHUNKS) { src = Wv; dst = g_wb + 2 * D_MODEL * D_MODEL;  off = gid - X_CHUNKS - 2 * W_CHUNKS; }
    else                                    { src = Wo; dst = g_wb + 3 * D_MODEL * D_MODEL;  off = gid - X_CHUNKS - 3 * W_CHUNKS; }

    const float4* s = reinterpret_cast<const float4*>(src) + (size_t)off * 2;
    const float4 f0 = s[0], f1 = s[1];
    uint4 d;
    d.x = pack_bf16x2(f0.x, f0.y); d.y = pack_bf16x2(f0.z, f0.w);
    d.z = pack_bf16x2(f1.x, f1.y); d.w = pack_bf16x2(f1.z, f1.w);
    *reinterpret_cast<uint4*>(dst + (size_t)off * 8) = d;
}

// ============================================================================
// Kernel 1: QKV projection, cp.async double-buffered bf16 tiles. (189us ver)
// ============================================================================
#define QKV_SMEM_BYTES ((2 * 128 * 64 + 2 * 64 * 64) * 2)   // 49152

__global__ void __launch_bounds__(256, 2) qkv_mma_kernel(
    const float* __restrict__ p_out, const float* __restrict__ p_out_inv)
{
    extern __shared__ __nv_bfloat16 smq[];
    __nv_bfloat16* a_b[2] = { smq,          smq + 8192 };
    __nv_bfloat16* b_b[2] = { smq + 16384,  smq + 16384 + 4096 };

    const int mode = blockIdx.z;   // 0=q, 1=k, 2=v
    const __nv_bfloat16* __restrict__ W = g_wb + (size_t)mode * D_MODEL * D_MODEL;
    __nv_bfloat16* __restrict__ out =
        (mode == 0) ? g_qb : (mode == 1) ? g_kb : g_vb;
    const float* __restrict__ Pm = (mode == 0) ? p_out_inv : p_out;

    const int tid  = threadIdx.x;
    const int lane = tid & 31;
    const int w    = tid >> 5;
    const int m0   = blockIdx.y * 128;
    const int n0   = blockIdx.x * 64;

    auto stage = [&](int ks, int buf) {
        const int k0 = ks * 64;
#pragma unroll
        for (int u = 0; u < 4; u++) {
            const int gid = u * 256 + tid;
            const int row = gid >> 3;
            const int c8  = gid & 7;
            cp_async16(smem_u32(a_b[buf] + row * 64 + ((c8 ^ (row & 7)) << 3)),
                       g_xb + (size_t)(m0 + row) * D_MODEL + k0 + c8 * 8);
        }
#pragma unroll
        for (int u = 0; u < 2; u++) {
            const int gid = u * 256 + tid;
            const int row = gid >> 3;
            const int c8  = gid & 7;
            cp_async16(smem_u32(b_b[buf] + row * 64 + ((c8 ^ (row & 7)) << 3)),
                       W + (size_t)(k0 + row) * D_MODEL + n0 + c8 * 8);
        }
    };

    float cf[8][4];
#pragma unroll
    for (int nt = 0; nt < 8; nt++)
#pragma unroll
        for (int c = 0; c < 4; c++) cf[nt][c] = 0.f;

    stage(0, 0);
    cp_commit();

    const int NKS = D_MODEL / 64;   // 8
    for (int ks = 0; ks < NKS; ks++) {
        const int buf = ks & 1;
        if (ks + 1 < NKS) {
            stage(ks + 1, buf ^ 1);
            cp_commit();
            cp_wait<1>();
        } else {
            cp_wait<0>();
        }
        __syncthreads();

        const __nv_bfloat16* a_s = a_b[buf];
        const __nv_bfloat16* b_s = b_b[buf];

        uint32_t qa[4][4];
        {
            const int mi = lane >> 3, rr = lane & 7;
            const int arow = w * 16 + ((mi & 1) << 3) + rr;
#pragma unroll
            for (int kt = 0; kt < 4; kt++) {
                const int ch = (kt * 2 + (mi >> 1)) ^ (arow & 7);
                ldsm_x4(qa[kt], smem_u32(a_s + arow * 64 + ch * 8));
            }
        }
        {
            const int j = lane >> 3, rr = lane & 7;
#pragma unroll
            for (int nt = 0; nt < 8; nt++) {
#pragma unroll
                for (int kt2 = 0; kt2 < 2; kt2++) {
                    const int brow = kt2 * 32 + j * 8 + rr;
                    const int ch = nt ^ (brow & 7);
                    uint32_t vb[4];
                    ldsm_x4_t(vb, smem_u32(b_s + brow * 64 + ch * 8));
                    mma_bf16(cf[nt], qa[kt2 * 2],     vb[0], vb[1]);
                    mma_bf16(cf[nt], qa[kt2 * 2 + 1], vb[2], vb[3]);
                }
            }
        }
        __syncthreads();
    }

    if (mode < 2) {
        const float* P = Pm + (m0 >> 9) * 16;
        float pm[16];
#pragma unroll
        for (int t = 0; t < 16; t++) pm[t] = P[t];
        const int gb = (lane & 1) * 2;
#pragma unroll
        for (int nt = 0; nt < 8; nt++) {
#pragma unroll
            for (int hf = 0; hf < 2; hf++) {
                const float v0 = cf[nt][hf * 2], v1 = cf[nt][hf * 2 + 1];
                const float p0 = __shfl_xor_sync(0xffffffffu, v0, 1);
                const float p1 = __shfl_xor_sync(0xffffffffu, v1, 1);
                const float a0 = (lane & 1) ? p0 : v0;
                const float a1 = (lane & 1) ? p1 : v1;
                const float a2 = (lane & 1) ? v0 : p0;
                const float a3 = (lane & 1) ? v1 : p1;
                cf[nt][hf * 2]     = a0 * pm[gb]     + a1 * pm[4 + gb]
                                   + a2 * pm[8 + gb] + a3 * pm[12 + gb];
                cf[nt][hf * 2 + 1] = a0 * pm[gb + 1]     + a1 * pm[4 + gb + 1]
                                   + a2 * pm[8 + gb + 1] + a3 * pm[12 + gb + 1];
            }
        }
    }
    if (mode == 0) {   // softmax scale * log2(e): 0.125 * 1.4426950
#pragma unroll
        for (int nt = 0; nt < 8; nt++)
#pragma unroll
            for (int c = 0; c < 4; c++) cf[nt][c] *= 0.18033688f;
    }

    const int row0 = m0 + w * 16 + (lane >> 2);
    const int row1 = row0 + 8;
#pragma unroll
    for (int nt = 0; nt < 8; nt++) {
        const int ng = n0 + nt * 8 + (lane & 3) * 2;
        const int h  = ng >> 6;
        const int c  = ng & 63;
        *reinterpret_cast<uint32_t*>(out + ((size_t)h * S_TOK + row0) * HD + c) =
            pack_bf16x2(cf[nt][0], cf[nt][1]);
        *reinterpret_cast<uint32_t*>(out + ((size_t)h * S_TOK + row1) * HD + c) =
            pack_bf16x2(cf[nt][2], cf[nt][3]);
    }
}

// ============================================================================
// Kernel 2: flash attention. Br=64, Bc=128, 4 warps, 2 CTAs/SM (reverted).
//   cp.async double-buffered K/V. Softmax interleaved with PV per k-chunk:
//   exp(16) -> pack(2 frags) -> 16 HMMA, x4 chunks; rs shuffles after PV.
// ============================================================================
#define ATTN_SMEM_BYTES ((64 * 64 + 4 * 128 * 64) * 2)   // 73728 B

__global__ void __launch_bounds__(128, 2) attn_kernel()
{
    extern __shared__ __nv_bfloat16 sm[];
    __nv_bfloat16* q_s = sm;
    __nv_bfloat16* k_b[2] = { sm + 4096,  sm + 4096 + 8192 };
    __nv_bfloat16* v_b[2] = { sm + 20480, sm + 20480 + 8192 };

    const int tid  = threadIdx.x;
    const int lane = tid & 31;
    const int w    = tid >> 5;
    const int h    = blockIdx.y;
    const int m0   = blockIdx.x * 64;

    const __nv_bfloat16* __restrict__ qg = g_qb + (size_t)h * S_TOK * HD;
    const __nv_bfloat16* __restrict__ kg = g_kb + (size_t)h * S_TOK * HD;
    const __nv_bfloat16* __restrict__ vg = g_vb + (size_t)h * S_TOK * HD;

    auto stage_kv = [&](int it, int buf) {
        const __nv_bfloat16* ks = kg + (size_t)(it * 128) * HD;
        const __nv_bfloat16* vs = vg + (size_t)(it * 128) * HD;
#pragma unroll
        for (int u = 0; u < 8; u++) {
            const int gid = u * 128 + tid;
            const int row = gid >> 3;
            const int c8  = gid & 7;
            const int so  = row * 64 + ((c8 ^ (row & 7)) << 3);
            cp_async16(smem_u32(k_b[buf] + so), ks + row * 64 + c8 * 8);
            cp_async16(smem_u32(v_b[buf] + so), vs + row * 64 + c8 * 8);
        }
    };

#pragma unroll
    for (int u = 0; u < 4; u++) {
        const int gid = u * 128 + tid;
        const int row = gid >> 3;
        const int c8  = gid & 7;
        uint4 d = *reinterpret_cast<const uint4*>(
            qg + (size_t)(m0 + row) * HD + c8 * 8);
        *reinterpret_cast<uint4*>(q_s + row * 64 + ((c8 ^ (row & 7)) << 3)) = d;
    }
    stage_kv(0, 0);
    cp_commit();
    __syncthreads();

    uint32_t qa[4][4];
    {
        const int mi = lane >> 3, rr = lane & 7;
        const int row = w * 16 + ((mi & 1) << 3) + rr;
#pragma unroll
        for (int kt = 0; kt < 4; kt++) {
            const int ch = (kt * 2 + (mi >> 1)) ^ (row & 7);
            ldsm_x4(qa[kt], smem_u32(q_s + row * 64 + ch * 8));
        }
    }

    float m_i0 = -1e30f, m_i1 = -1e30f, l0 = 0.f, l1 = 0.f;
    float of[8][4];
#pragma unroll
    for (int nt = 0; nt < 8; nt++)
#pragma unroll
        for (int c = 0; c < 4; c++) of[nt][c] = 0.f;

    const int NIT = S_TOK / 128;   // 32
    for (int it = 0; it < NIT; it++) {
        const int buf = it & 1;
        if (it + 1 < NIT) {
            stage_kv(it + 1, buf ^ 1);
            cp_commit();
            cp_wait<1>();
        } else {
            cp_wait<0>();
        }
        __syncthreads();

        const __nv_bfloat16* k_s = k_b[buf];
        const __nv_bfloat16* v_s = v_b[buf];

        // ---- S = Q K^T : 16 n-tiles x 4 k-steps (non-trans K frags) ----
        float sf[16][4];
#pragma unroll
        for (int nt = 0; nt < 16; nt++)
#pragma unroll
            for (int c = 0; c < 4; c++) sf[nt][c] = 0.f;

        {
            const int j = lane >> 3, rr = lane & 7;
#pragma unroll
            for (int nt = 0; nt < 16; nt++) {
                const int srow = nt * 8 + rr;
                uint32_t b[8];
                const int ch0 = (j)     ^ (srow & 7);
                const int ch1 = (4 + j) ^ (srow & 7);
                ldsm_x4(b,     smem_u32(k_s + srow * 64 + ch0 * 8));
                ldsm_x4(b + 4, smem_u32(k_s + srow * 64 + ch1 * 8));
                mma_bf16(sf[nt], qa[0], b[0], b[1]);
                mma_bf16(sf[nt], qa[1], b[2], b[3]);
                mma_bf16(sf[nt], qa[2], b[4], b[5]);
                mma_bf16(sf[nt], qa[3], b[6], b[7]);
            }
        }

        // ---- row max (quad reduction) ----
        float mx0 = sf[0][0], mx1 = sf[0][2];
#pragma unroll
        for (int nt = 0; nt < 16; nt++) {
            mx0 = fmaxf(mx0, fmaxf(sf[nt][0], sf[nt][1]));
            mx1 = fmaxf(mx1, fmaxf(sf[nt][2], sf[nt][3]));
        }
        mx0 = fmaxf(mx0, __shfl_xor_sync(0xffffffffu, mx0, 1));
        mx0 = fmaxf(mx0, __shfl_xor_sync(0xffffffffu, mx0, 2));
        mx1 = fmaxf(mx1, __shfl_xor_sync(0xffffffffu, mx1, 1));
        mx1 = fmaxf(mx1, __shfl_xor_sync(0xffffffffu, mx1, 2));

        const float mn0 = fmaxf(m_i0, mx0);
        const float mn1 = fmaxf(m_i1, mx1);
        const float al0 = exp2f(m_i0 - mn0);
        const float al1 = exp2f(m_i1 - mn1);
        m_i0 = mn0; m_i1 = mn1;

        // ---- hoisted O rescale (independent of exps) ----
#pragma unroll
        for (int nt = 0; nt < 8; nt++) {
            of[nt][0] *= al0; of[nt][1] *= al0;
            of[nt][2] *= al1; of[nt][3] *= al1;
        }

        // ---- interleaved softmax + PV: per k-chunk exp->pack->mma ----
        float rs0 = 0.f, rs1 = 0.f;
        {
            const int j = lane >> 3, rr = lane & 7;
#pragma unroll
            for (int kt2 = 0; kt2 < 4; kt2++) {
                uint32_t pa0[4], pa1[4];
#pragma unroll
                for (int q2 = 0; q2 < 2; q2++) {   // nt pairs (4kt2+2q2, +1)
                    const int nta = kt2 * 4 + q2 * 2;
                    const float e0 = exp2f(sf[nta][0] - mn0);
                    const float e1 = exp2f(sf[nta][1] - mn0);
                    const float e2 = exp2f(sf[nta][2] - mn1);
                    const float e3 = exp2f(sf[nta][3] - mn1);
                    const float f0 = exp2f(sf[nta + 1][0] - mn0);
                    const float f1 = exp2f(sf[nta + 1][1] - mn0);
                    const float f2 = exp2f(sf[nta + 1][2] - mn1);
                    const float f3 = exp2f(sf[nta + 1][3] - mn1);
                    rs0 += e0 + e1; rs1 += e2 + e3;
                    rs0 += f0 + f1; rs1 += f2 + f3;
                    uint32_t* pp = q2 ? pa1 : pa0;
                    pp[0] = pack_bf16x2(e0, e1);
                    pp[1] = pack_bf16x2(e2, e3);
                    pp[2] = pack_bf16x2(f0, f1);
                    pp[3] = pack_bf16x2(f2, f3);
                }
#pragma unroll
                for (int nt = 0; nt < 8; nt++) {
                    const int vrow = kt2 * 32 + j * 8 + rr;
                    uint32_t vb[4];
                    const int ch = nt ^ (vrow & 7);
                    ldsm_x4_t(vb, smem_u32(v_s + vrow * 64 + ch * 8));
                    mma_bf16(of[nt], pa0, vb[0], vb[1]);
                    mma_bf16(of[nt], pa1, vb[2], vb[3]);
                }
            }
        }

        // ---- l update (shuffles after PV; same accumulation order) ----
        rs0 += __shfl_xor_sync(0xffffffffu, rs0, 1);
        rs0 += __shfl_xor_sync(0xffffffffu, rs0, 2);
        rs1 += __shfl_xor_sync(0xffffffffu, rs1, 1);
        rs1 += __shfl_xor_sync(0xffffffffu, rs1, 2);
        l0 = l0 * al0 + rs0;
        l1 = l1 * al1 + rs1;

        __syncthreads();
    }

    const float inv0 = 1.0f / l0;
    const float inv1 = 1.0f / l1;
    const int row0 = m0 + w * 16 + (lane >> 2);
    const int row1 = row0 + 8;
    const int cbase = h * HD + (lane & 3) * 2;
#pragma unroll
    for (int nt = 0; nt < 8; nt++) {
        const int col = cbase + nt * 8;
        *reinterpret_cast<uint32_t*>(g_ob + (size_t)row0 * D_MODEL + col) =
            pack_bf16x2(of[nt][0] * inv0, of[nt][1] * inv0);
        *reinterpret_cast<uint32_t*>(g_ob + (size_t)row1 * D_MODEL + col) =
            pack_bf16x2(of[nt][2] * inv1, of[nt][3] * inv1);
    }
}

// ============================================================================
// Kernel 3: output projection, cp.async double-buffered; bias + residual.
// ============================================================================
#define PROJ_SMEM_BYTES ((2 * 128 * 64 + 2 * 64 * 128) * 2)   // 65536

__global__ void __launch_bounds__(256) proj_mma_kernel(
    const float* __restrict__ bo,
    const float* __restrict__ hs, float* __restrict__ outp)
{
    extern __shared__ __nv_bfloat16 smp[];
    __nv_bfloat16* a_b[2] = { smp,          smp + 8192 };
    __nv_bfloat16* b_b[2] = { smp + 16384,  smp + 16384 + 8192 };

    const __nv_bfloat16* __restrict__ Wo = g_wb + (size_t)3 * D_MODEL * D_MODEL;

    const int tid  = threadIdx.x;
    const int lane = tid & 31;
    const int w    = tid >> 5;
    const int m0   = blockIdx.y * 128;
    const int n0   = blockIdx.x * 128;

    auto stage = [&](int ks, int buf) {
        const int k0 = ks * 64;
#pragma unroll
        for (int u = 0; u < 4; u++) {
            const int gid = u * 256 + tid;
            const int row = gid >> 3;
            const int c8  = gid & 7;
            cp_async16(smem_u32(a_b[buf] + row * 64 + ((c8 ^ (row & 7)) << 3)),
                       g_ob + (size_t)(m0 + row) * D_MODEL + k0 + c8 * 8);
        }
#pragma unroll
        for (int u = 0; u < 4; u++) {
            const int gid = u * 256 + tid;
            const int row = gid >> 4;
            const int c16 = gid & 15;
            cp_async16(smem_u32(b_b[buf] + row * 128 + ((c16 ^ (row & 7)) << 3)),
                       Wo + (size_t)(k0 + row) * D_MODEL + n0 + c16 * 8);
        }
    };

    float cf[16][4];
#pragma unroll
    for (int nt = 0; nt < 16; nt++)
#pragma unroll
        for (int c = 0; c < 4; c++) cf[nt][c] = 0.f;

    stage(0, 0);
    cp_commit();

    const int NKS = D_MODEL / 64;   // 8
    for (int ks = 0; ks < NKS; ks++) {
        const int buf = ks & 1;
        if (ks + 1 < NKS) {
            stage(ks + 1, buf ^ 1);
            cp_commit();
            cp_wait<1>();
        } else {
            cp_wait<0>();
        }
        __syncthreads();

        const __nv_bfloat16* a_s = a_b[buf];
        const __nv_bfloat16* b_s = b_b[buf];

        uint32_t qa[4][4];
        {
            const int mi = lane >> 3, rr = lane & 7;
            const int arow = w * 16 + ((mi & 1) << 3) + rr;
#pragma unroll
            for (int kt = 0; kt < 4; kt++) {
                const int ch = (kt * 2 + (mi >> 1)) ^ (arow & 7);
                ldsm_x4(qa[kt], smem_u32(a_s + arow * 64 + ch * 8));
            }
        }
        {
            const int j = lane >> 3, rr = lane & 7;
#pragma unroll
            for (int nt = 0; nt < 16; nt++) {
#pragma unroll
                for (int kt2 = 0; kt2 < 2; kt2++) {
                    const int brow = kt2 * 32 + j * 8 + rr;
                    const int ch = nt ^ (brow & 7);
                    uint32_t vb[4];
                    ldsm_x4_t(vb, smem_u32(b_s + brow * 128 + ch * 8));
                    mma_bf16(cf[nt], qa[kt2 * 2],     vb[0], vb[1]);
                    mma_bf16(cf[nt], qa[kt2 * 2 + 1], vb[2], vb[3]);
                }
            }
        }
        __syncthreads();
    }

    const int row0 = m0 + w * 16 + (lane >> 2);
    const int row1 = row0 + 8;
#pragma unroll
    for (int nt = 0; nt < 16; nt++) {
        const int col = n0 + nt * 8 + (lane & 3) * 2;
        const float2 bb = *reinterpret_cast<const float2*>(bo + col);
        const float2 r0 = *reinterpret_cast<const float2*>(
            hs + (size_t)row0 * D_MODEL + col);
        const float2 r1 = *reinterpret_cast<const float2*>(
            hs + (size_t)row1 * D_MODEL + col);
        *reinterpret_cast<float2*>(outp + (size_t)row0 * D_MODEL + col) =
            make_float2(cf[nt][0] + bb.x + r0.x, cf[nt][1] + bb.y + r0.y);
        *reinterpret_cast<float2*>(outp + (size_t)row1 * D_MODEL + col) =
            make_float2(cf[nt][2] + bb.x + r1.x, cf[nt][3] + bb.y + r1.y);
    }
}

// ============================================================================
// Launch
// ============================================================================
extern "C" void kernel_launch(void* const* d_in, const int* in_sizes, int n_in,
                              void* d_out, int out_size)
{
    const float* hs        = (const float*)d_in[0];
    const float* p_out     = (const float*)d_in[1];
    const float* p_out_inv = (const float*)d_in[2];
    const float* Wq        = (const float*)d_in[3];
    const float* Wk        = (const float*)d_in[4];
    const float* Wv        = (const float*)d_in[5];
    const float* Wo        = (const float*)d_in[6];
    const float* bo        = (const float*)d_in[7];
    float* out             = (float*)d_out;

    // >48KB dynamic smem opt-ins (host attributes; idempotent, graph-safe).
    cudaFuncSetAttribute(attn_kernel,
                         cudaFuncAttributeMaxDynamicSharedMemorySize,
                         ATTN_SMEM_BYTES);
    cudaFuncSetAttribute(proj_mma_kernel,
                         cudaFuncAttributeMaxDynamicSharedMemorySize,
                         PROJ_SMEM_BYTES);
    cudaFuncSetAttribute(qkv_mma_kernel,
                         cudaFuncAttributeMaxDynamicSharedMemorySize,
                         QKV_SMEM_BYTES);

    convert_kernel<<<1536, 256>>>(hs, Wq, Wk, Wv, Wo);
    qkv_mma_kernel<<<dim3(8, 32, 3), 256, QKV_SMEM_BYTES>>>(p_out, p_out_inv);
    attn_kernel<<<dim3(64, 8), 128, ATTN_SMEM_BYTES>>>();
    proj_mma_kernel<<<dim3(4, 32), 256, PROJ_SMEM_BYTES>>>(bo, hs, out);
}